// round 16
// baseline (speedup 1.0000x reference)
#include <cuda_runtime.h>
#include <cuda_fp16.h>
#include <mma.h>
#include <math.h>

using namespace nvcuda;

#define NN   50000
#define EE   1600000
#define ET   (EE + NN)
#define INC  256
#define HC   128
#define H1   4
#define C1   32
#define BN_EPS 1e-5f
#define NB   196            // ceil(NN/256)
#define NROWS 50048         // 391*128, padded rows for GEMM1 stores

// ---------------- scratch ----------------
__device__ __half  g_W1h [INC * HC];     // fp16 W1
__device__ float   g_xs1 [NROWS * HC];   // fp32 GEMM1 out (padded)
__device__ uint2   g_xs1q[NN * 32];      // quad mirror: [n][c] = (x[c],x[c+32] | x[c+64],x[c+96])
__device__ __half  g_xs2h[NN * C1];
__device__ float   g_als1[NN * H1];
__device__ float   g_ald1[NN * H1];
__device__ float   g_als2[NN];
__device__ float   g_ald2[NN];
__device__ int     g_deg   [NN];
__device__ int     g_rowptr[NN + 1];
__device__ int     g_cursor[NN];
__device__ int     g_bsum[NB];
__device__ int     g_boff[NB];
__device__ int2    g_slot[ET];           // 8B: (src, ea bits)
__device__ float   g_partial[512];
__device__ float   g_mean;
__device__ float   g_k1v[H1];
__device__ float   g_k2;

// ---------------- helpers ----------------
__device__ __forceinline__ unsigned h2u(__half2 h) { return *(unsigned*)&h; }
__device__ __forceinline__ float leaky(float x) { return x > 0.f ? x : 0.2f * x; }
__device__ __forceinline__ float elu(float x)   { return x > 0.f ? x : expm1f(x); }
__device__ __forceinline__ float wexp(float x)  { return __expf(fminf(x, 80.f)); }

// ---------------- fp16 W1 conversion ----------------
__global__ void convW1_kernel(const float* __restrict__ W1) {
    int i = blockIdx.x * blockDim.x + threadIdx.x;
    if (i >= INC * HC / 8) return;
    const float4* p = (const float4*)W1 + (size_t)i * 2;
    float4 a = p[0], b = p[1];
    uint4 u;
    u.x = h2u(__floats2half2_rn(a.x, a.y));
    u.y = h2u(__floats2half2_rn(a.z, a.w));
    u.z = h2u(__floats2half2_rn(b.x, b.y));
    u.w = h2u(__floats2half2_rn(b.z, b.w));
    ((uint4*)g_W1h)[i] = u;
}

// ---------------- GEMM1: wmma fp16->fp32, converts x fp32->fp16 in-flight ----------
__global__ void __launch_bounds__(256) sgemm1_wmma(const float* __restrict__ x) {
    __shared__ __align__(32) __half As[128][32];    // ld=32
    __shared__ __align__(32) __half Bs[16][144];    // ld=144
    int tid = threadIdx.x;
    int w = tid >> 5, wr = w >> 1, wc = w & 1;
    int brow = blockIdx.x;

    wmma::fragment<wmma::accumulator, 16, 16, 16, float> cf[2][4];
#pragma unroll
    for (int mi = 0; mi < 2; mi++)
#pragma unroll
        for (int ni = 0; ni < 4; ni++) wmma::fill_fragment(cf[mi][ni], 0.f);

    int rA = tid >> 1, segA = (tid & 1) * 8;
    int ag = brow * 128 + rA;
    int qB = tid >> 4, cB = (tid & 15) * 8;

    for (int k0 = 0; k0 < INC; k0 += 16) {
        uint4 ua = make_uint4(0, 0, 0, 0);
        if (ag < NN) {
            const float* xp = x + (size_t)ag * INC + k0 + segA;
            float4 f0 = *(const float4*)(xp);
            float4 f1 = *(const float4*)(xp + 4);
            ua.x = h2u(__floats2half2_rn(f0.x, f0.y));
            ua.y = h2u(__floats2half2_rn(f0.z, f0.w));
            ua.z = h2u(__floats2half2_rn(f1.x, f1.y));
            ua.w = h2u(__floats2half2_rn(f1.z, f1.w));
        }
        *(uint4*)&As[rA][segA] = ua;
        *(uint4*)&Bs[qB][cB] = *(const uint4*)(g_W1h + (size_t)(k0 + qB) * HC + cB);
        __syncthreads();

        wmma::fragment<wmma::matrix_b, 16, 16, 16, __half, wmma::row_major> bf[4];
#pragma unroll
        for (int ni = 0; ni < 4; ni++)
            wmma::load_matrix_sync(bf[ni], &Bs[0][wc * 64 + ni * 16], 144);
#pragma unroll
        for (int mi = 0; mi < 2; mi++) {
            wmma::fragment<wmma::matrix_a, 16, 16, 16, __half, wmma::row_major> af;
            wmma::load_matrix_sync(af, &As[wr * 32 + mi * 16][0], 32);
#pragma unroll
            for (int ni = 0; ni < 4; ni++)
                wmma::mma_sync(cf[mi][ni], af, bf[ni], cf[mi][ni]);
        }
        __syncthreads();
    }
#pragma unroll
    for (int mi = 0; mi < 2; mi++)
#pragma unroll
        for (int ni = 0; ni < 4; ni++)
            wmma::store_matrix_sync(
                g_xs1 + (size_t)(brow * 128 + wr * 32 + mi * 16) * HC + wc * 64 + ni * 16,
                cf[mi][ni], HC, wmma::mem_row_major);
}

// ---------------- post1: al1 dots + quad-packed mirror; 2 threads/node --------------
__global__ void post1_kernel(const float* __restrict__ as1, const float* __restrict__ ad1) {
    int idx = blockIdx.x * blockDim.x + threadIdx.x;
    if (idx >= NN * 2) return;
    int n = idx >> 1, q = idx & 1;          // q selects channels [q*16, q*16+16)
    const float* base = g_xs1 + (size_t)n * HC;

    float4 v[4][4];
    float s[4], d[4];
#pragma unroll
    for (int h = 0; h < 4; h++) {
        s[h] = 0.f; d[h] = 0.f;
#pragma unroll
        for (int g = 0; g < 4; g++) {
            int off = h * 32 + q * 16 + g * 4;
            float4 xv = *(const float4*)(base + off);
            float4 av = *(const float4*)(as1 + off);
            float4 dv = *(const float4*)(ad1 + off);
            v[h][g] = xv;
            s[h] += xv.x * av.x + xv.y * av.y + xv.z * av.z + xv.w * av.w;
            d[h] += xv.x * dv.x + xv.y * dv.y + xv.z * dv.z + xv.w * dv.w;
        }
    }
    uint2* op = g_xs1q + (size_t)n * 32 + q * 16;
#pragma unroll
    for (int g = 0; g < 4; g++) {
        float4 h0 = v[0][g], h1 = v[1][g], h2v = v[2][g], h3 = v[3][g];
        op[g * 4 + 0] = make_uint2(h2u(__floats2half2_rn(h0.x, h1.x)),
                                   h2u(__floats2half2_rn(h2v.x, h3.x)));
        op[g * 4 + 1] = make_uint2(h2u(__floats2half2_rn(h0.y, h1.y)),
                                   h2u(__floats2half2_rn(h2v.y, h3.y)));
        op[g * 4 + 2] = make_uint2(h2u(__floats2half2_rn(h0.z, h1.z)),
                                   h2u(__floats2half2_rn(h2v.z, h3.z)));
        op[g * 4 + 3] = make_uint2(h2u(__floats2half2_rn(h0.w, h1.w)),
                                   h2u(__floats2half2_rn(h2v.w, h3.w)));
    }
#pragma unroll
    for (int h = 0; h < 4; h++) {
        s[h] += __shfl_xor_sync(0xffffffffu, s[h], 1);
        d[h] += __shfl_xor_sync(0xffffffffu, d[h], 1);
    }
    if (q == 0) {
#pragma unroll
        for (int h = 0; h < 4; h++) {
            g_als1[n * 4 + h] = s[h];
            g_ald1[n * 4 + h] = d[h];
        }
    }
}

// ---------------- CSR build (branch B) ----------------
__global__ void init_deg_kernel() {
    int i = blockIdx.x * blockDim.x + threadIdx.x;
    if (i < NN) g_deg[i] = 1;
}

__global__ void hist_mean_kernel(const int* __restrict__ ei, const float* __restrict__ ea) {
    __shared__ float s[256];
    float v = 0.f;
    for (int e = blockIdx.x * blockDim.x + threadIdx.x; e < EE; e += gridDim.x * blockDim.x) {
        atomicAdd(&g_deg[ei[EE + e]], 1);
        v += ea[e];
    }
    s[threadIdx.x] = v; __syncthreads();
    for (int o = 128; o > 0; o >>= 1) {
        if (threadIdx.x < o) s[threadIdx.x] += s[threadIdx.x + o];
        __syncthreads();
    }
    if (threadIdx.x == 0) g_partial[blockIdx.x] = s[0];
}

__global__ void mean_fin_kernel(const float* __restrict__ We1, const float* __restrict__ ae1,
                                const float* __restrict__ We2, const float* __restrict__ ae2) {
    __shared__ float s[512];
    int t = threadIdx.x;
    s[t] = g_partial[t]; __syncthreads();
    for (int o = 256; o > 0; o >>= 1) {
        if (t < o) s[t] += s[t + o];
        __syncthreads();
    }
    if (t == 0) g_mean = s[0] / (float)EE;
    if (t < H1) {
        float k = 0.f;
        for (int c = 0; c < C1; c++) k += We1[t * C1 + c] * ae1[t * C1 + c];
        g_k1v[t] = k;
    }
    if (t == H1) {
        float k = 0.f;
        for (int c = 0; c < C1; c++) k += We2[c] * ae2[c];
        g_k2 = k;
    }
}

__global__ void scan_part_kernel() {
    __shared__ int s[256];
    int t = threadIdx.x, b = blockIdx.x;
    int i = b * 256 + t;
    int v = (i < NN) ? g_deg[i] : 0;
    s[t] = v; __syncthreads();
    for (int o = 128; o > 0; o >>= 1) {
        if (t < o) s[t] += s[t + o];
        __syncthreads();
    }
    if (t == 0) g_bsum[b] = s[0];
}

__global__ void scan_mid_kernel() {
    __shared__ int s[256];
    int t = threadIdx.x;
    int v = (t < NB) ? g_bsum[t] : 0;
    s[t] = v; __syncthreads();
    for (int o = 1; o < 256; o <<= 1) {
        int u = (t >= o) ? s[t - o] : 0;
        __syncthreads();
        s[t] += u;
        __syncthreads();
    }
    if (t < NB) g_boff[t] = s[t] - v;
}

__global__ void scan_fin_kernel() {
    __shared__ int s[256];
    int t = threadIdx.x, b = blockIdx.x;
    int i = b * 256 + t;
    int v = (i < NN) ? g_deg[i] : 0;
    s[t] = v; __syncthreads();
    for (int o = 1; o < 256; o <<= 1) {
        int u = (t >= o) ? s[t - o] : 0;
        __syncthreads();
        s[t] += u;
        __syncthreads();
    }
    int excl = s[t] - v + g_boff[b];
    if (i < NN) { g_rowptr[i] = excl; g_cursor[i] = excl; }
    if (b == 0 && t == 0) g_rowptr[NN] = ET;
}

// ---------------- scatter: (src, ea) into 8B slots ----------------
__global__ void scatter_perm_kernel(const int* __restrict__ ei, const float* __restrict__ ea) {
    float mn = g_mean;
    for (int idx = blockIdx.x * blockDim.x + threadIdx.x; idx < ET; idx += gridDim.x * blockDim.x) {
        int srcn, dstn; float eav;
        if (idx < EE) {
            srcn = ei[idx];
            dstn = ei[EE + idx];
            eav  = ea[idx];
        } else {
            srcn = dstn = idx - EE;
            eav  = mn;
        }
        int slot = atomicAdd(&g_cursor[dstn], 1);
        g_slot[slot] = make_int2(srcn, __float_as_int(eav));
    }
}

// ---------------- agg1 + gemm2 + al2, fully fused (warp per node) ----------------
__global__ void __launch_bounds__(256) agg1_gemm2_kernel(
        const float* __restrict__ b1, const float* __restrict__ g1,
        const float* __restrict__ be1, const float* __restrict__ W2,
        const float* __restrict__ as2, const float* __restrict__ ad2) {
    __shared__ float  Ws[HC * C1];     // 16KB
    __shared__ float4 sw[8][32];       // 4KB
    __shared__ int    ssrc[8][32];     // 1KB
    __shared__ float  sh1[8][HC];      // 4KB
    int tid = threadIdx.x;
    for (int i = tid; i < HC * C1; i += blockDim.x) Ws[i] = W2[i];
    __syncthreads();

    int wi   = tid >> 5;
    int lane = tid & 31;
    int n    = blockIdx.x * 8 + wi;
    if (n >= NN) return;
    int beg = g_rowptr[n], end = g_rowptr[n + 1];
    float4 ald = *(const float4*)(g_ald1 + n * 4);
    float k0 = g_k1v[0], k1 = g_k1v[1], k2 = g_k1v[2], k3 = g_k1v[3];

    float acc0 = 0.f, acc1 = 0.f, acc2 = 0.f, acc3 = 0.f;
    float den0 = 0.f, den1 = 0.f, den2 = 0.f, den3 = 0.f;

    for (int c0 = beg; c0 < end; c0 += 32) {
        int m = end - c0; if (m > 32) m = 32;
        if (lane < m) {
            int2 se = g_slot[c0 + lane];
            float4 als = *(const float4*)(g_als1 + se.x * 4);
            float eav = __int_as_float(se.y);
            float4 w;
            w.x = wexp(leaky(als.x + ald.x + k0 * eav));
            w.y = wexp(leaky(als.y + ald.y + k1 * eav));
            w.z = wexp(leaky(als.z + ald.z + k2 * eav));
            w.w = wexp(leaky(als.w + ald.w + k3 * eav));
            sw[wi][lane] = w;
            ssrc[wi][lane] = se.x;
        }
        __syncwarp();
        for (int i = 0; i < m; i++) {
            float4 w = sw[wi][i];
            int s = ssrc[wi][i];
            uint2 xv = g_xs1q[(size_t)s * 32 + lane];
            float2 x01 = __half22float2(*(__half2*)&xv.x);   // (head0, head1)
            float2 x23 = __half22float2(*(__half2*)&xv.y);   // (head2, head3)
            acc0 += w.x * x01.x;  den0 += w.x;
            acc1 += w.y * x01.y;  den1 += w.y;
            acc2 += w.z * x23.x;  den2 += w.z;
            acc3 += w.w * x23.y;  den3 += w.w;
        }
        __syncwarp();
    }

    // bias + bn + elu -> h1 (fp32) staged into smem
    float inv = rsqrtf(1.f + BN_EPS);
#pragma unroll
    for (int h = 0; h < 4; h++) {
        float a = (h == 0) ? acc0 : (h == 1) ? acc1 : (h == 2) ? acc2 : acc3;
        float d = (h == 0) ? den0 : (h == 1) ? den1 : (h == 2) ? den2 : den3;
        int c = h * 32 + lane;
        float v = a / (d + 1e-16f) + b1[c];
        v = v * (g1[c] * inv) + be1[c];
        sh1[wi][c] = elu(v);
    }
    __syncwarp();

    // gemm2: xs2[lane] = sum_k h1[k] * W2[k][lane]
    float s2 = 0.f;
    const float* hp = sh1[wi];
#pragma unroll 8
    for (int k = 0; k < HC; k++) s2 += hp[k] * Ws[k * C1 + lane];
    g_xs2h[(size_t)n * C1 + lane] = __float2half_rn(s2);

    // al2 warp reduction
    float ps = s2 * as2[lane];
    float pd = s2 * ad2[lane];
#pragma unroll
    for (int off = 16; off > 0; off >>= 1) {
        ps += __shfl_xor_sync(0xffffffffu, ps, off);
        pd += __shfl_xor_sync(0xffffffffu, pd, off);
    }
    if (lane == 0) { g_als2[n] = ps; g_ald2[n] = pd; }
}

// ---------------- agg2: warp/node, smem-staged weights + bn+elu + heads ----------
__global__ void agg2_heads_kernel(const float* __restrict__ b2, const float* __restrict__ g2,
                                  const float* __restrict__ be2,
                                  const float* __restrict__ Wc1, const float* __restrict__ bc1,
                                  const float* __restrict__ Wc2, const float* __restrict__ bc2,
                                  const float* __restrict__ Wr1, const float* __restrict__ br1,
                                  const float* __restrict__ Wr2, const float* __restrict__ br2,
                                  float* __restrict__ out) {
    __shared__ float sWc1[C1 * 16], sWr1[C1 * 16];
    __shared__ float sWc2[32], sWr2[16];
    __shared__ float sbc1[16], sbr1[16], sbc2[2], sbr2v[1];
    __shared__ float sh[8][32];
    __shared__ float sw2[8][32];
    __shared__ int   ssrc2[8][32];
    int t = threadIdx.x;
    for (int i = t; i < C1 * 16; i += blockDim.x) { sWc1[i] = Wc1[i]; sWr1[i] = Wr1[i]; }
    if (t < 32) sWc2[t] = Wc2[t];
    if (t < 16) { sWr2[t] = Wr2[t]; sbc1[t] = bc1[t]; sbr1[t] = br1[t]; }
    if (t < 2)  sbc2[t] = bc2[t];
    if (t == 32) sbr2v[0] = br2[0];
    __syncthreads();

    int wi   = t >> 5;
    int lane = t & 31;
    int n    = blockIdx.x * 8 + wi;
    if (n >= NN) return;
    int beg = g_rowptr[n], end = g_rowptr[n + 1];
    float ald = g_ald2[n];
    float k2  = g_k2;

    float den = 0.f, acc = 0.f;
    for (int c0 = beg; c0 < end; c0 += 32) {
        int m = end - c0; if (m > 32) m = 32;
        if (lane < m) {
            int2 se = g_slot[c0 + lane];
            sw2[wi][lane] = wexp(leaky(g_als2[se.x] + ald + k2 * __int_as_float(se.y)));
            ssrc2[wi][lane] = se.x;
        }
        __syncwarp();
        for (int i = 0; i < m; i++) {
            float w = sw2[wi][i];
            int s = ssrc2[wi][i];
            acc += w * __half2float(g_xs2h[(size_t)s * C1 + lane]);
            den += w;
        }
        __syncwarp();
    }
    float v = acc / (den + 1e-16f) + b2[lane];
    v = v * (g2[lane] * rsqrtf(1.f + BN_EPS)) + be2[lane];
    float h = elu(v);
    out[3 * NN + (size_t)n * C1 + lane] = h;
    sh[wi][lane] = h;
    __syncwarp();

    int j = lane & 15;
    const float* W = (lane < 16) ? sWc1 : sWr1;
    float tt = (lane < 16) ? sbc1[j] : sbr1[j];
#pragma unroll
    for (int c = 0; c < C1; c++) tt += sh[wi][c] * W[c * 16 + j];
    tt = fmaxf(tt, 0.f);
    float pa = (lane < 16) ? tt * sWc2[j * 2 + 0] : tt * sWr2[j];
    float pb = (lane < 16) ? tt * sWc2[j * 2 + 1] : 0.f;
#pragma unroll
    for (int off = 8; off > 0; off >>= 1) {
        pa += __shfl_xor_sync(0xffffffffu, pa, off);
        pb += __shfl_xor_sync(0xffffffffu, pb, off);
    }
    if (lane == 0) {
        out[(size_t)n * 2 + 0] = pa + sbc2[0];
        out[(size_t)n * 2 + 1] = pb + sbc2[1];
    }
    if (lane == 16) {
        out[2 * NN + n] = pa + sbr2v[0];
    }
}

// ---------------- launch (stream-forked graph) ----------------
extern "C" void kernel_launch(void* const* d_in, const int* in_sizes, int n_in,
                              void* d_out, int out_size) {
    const float* x   = (const float*)d_in[0];
    const int*   ei  = (const int*)d_in[1];     // int32 (JAX x64 disabled)
    const float* ea  = (const float*)d_in[2];
    const float* W1  = (const float*)d_in[3];
    const float* as1 = (const float*)d_in[4];
    const float* ad1 = (const float*)d_in[5];
    const float* We1 = (const float*)d_in[6];
    const float* ae1 = (const float*)d_in[7];
    const float* b1  = (const float*)d_in[8];
    const float* g1  = (const float*)d_in[9];
    const float* be1 = (const float*)d_in[10];
    const float* W2  = (const float*)d_in[11];
    const float* as2 = (const float*)d_in[12];
    const float* ad2 = (const float*)d_in[13];
    const float* We2 = (const float*)d_in[14];
    const float* ae2 = (const float*)d_in[15];
    const float* b2  = (const float*)d_in[16];
    const float* g2  = (const float*)d_in[17];
    const float* be2 = (const float*)d_in[18];
    const float* Wc1 = (const float*)d_in[19];
    const float* bc1 = (const float*)d_in[20];
    const float* Wc2 = (const float*)d_in[21];
    const float* bc2 = (const float*)d_in[22];
    const float* Wr1 = (const float*)d_in[23];
    const float* br1 = (const float*)d_in[24];
    const float* Wr2 = (const float*)d_in[25];
    const float* br2 = (const float*)d_in[26];
    float* out = (float*)d_out;

    cudaStream_t sB;
    cudaStreamCreateWithFlags(&sB, cudaStreamNonBlocking);
    cudaEvent_t eFork, eJoin;
    cudaEventCreateWithFlags(&eFork, cudaEventDisableTiming);
    cudaEventCreateWithFlags(&eJoin, cudaEventDisableTiming);

    cudaEventRecord(eFork, 0);
    cudaStreamWaitEvent(sB, eFork, 0);

    // Branch B (CSR + scatter permutation)
    init_deg_kernel<<<(NN + 255) / 256, 256, 0, sB>>>();
    hist_mean_kernel<<<512, 256, 0, sB>>>(ei, ea);
    mean_fin_kernel<<<1, 512, 0, sB>>>(We1, ae1, We2, ae2);
    scan_part_kernel<<<NB, 256, 0, sB>>>();
    scan_mid_kernel<<<1, 256, 0, sB>>>();
    scan_fin_kernel<<<NB, 256, 0, sB>>>();
    scatter_perm_kernel<<<2048, 256, 0, sB>>>(ei, ea);

    // Branch A (fp16 GEMM1 chain) on main stream
    convW1_kernel<<<(INC * HC / 8 + 255) / 256, 256>>>(W1);
    sgemm1_wmma<<<(NN + 127) / 128, 256>>>(x);
    post1_kernel<<<(NN * 2 + 255) / 256, 256>>>(as1, ad1);

    cudaEventRecord(eJoin, sB);
    cudaStreamWaitEvent(0, eJoin, 0);

    // Joined tail on main stream
    agg1_gemm2_kernel<<<(NN + 7) / 8, 256>>>(b1, g1, be1, W2, as2, ad2);
    agg2_heads_kernel<<<(NN + 7) / 8, 256>>>(b2, g2, be2,
        Wc1, bc1, Wc2, bc2, Wr1, br1, Wr2, br2, out);

    cudaEventDestroy(eFork);
    cudaEventDestroy(eJoin);
    // sB intentionally not destroyed during capture.
}

// round 17
// speedup vs baseline: 1.0366x; 1.0366x over previous
#include <cuda_runtime.h>
#include <cuda_fp16.h>
#include <mma.h>
#include <math.h>

using namespace nvcuda;

#define NN   50000
#define EE   1600000
#define ET   (EE + NN)
#define INC  256
#define HC   128
#define H1   4
#define C1   32
#define BN_EPS 1e-5f
#define NB   196            // ceil(NN/256)

// ---------------- scratch ----------------
__device__ __half  g_W1h [INC * HC];     // fp16 W1
__device__ uint2   g_xs1q[NN * 32];      // quad mirror: [n][c] = (x[c],x[c+32] | x[c+64],x[c+96])
__device__ __half  g_xs2h[NN * C1];
__device__ float   g_als1[NN * H1];
__device__ float   g_ald1[NN * H1];
__device__ float   g_als2[NN];
__device__ float   g_ald2[NN];
__device__ int     g_deg   [NN];
__device__ int     g_rowptr[NN + 1];
__device__ int     g_cursor[NN];
__device__ int     g_bsum[NB];
__device__ int     g_boff[NB];
__device__ int2    g_slot[ET];           // 8B: (src, ea bits)
__device__ float   g_partial[512];
__device__ float   g_mean;
__device__ float   g_k1v[H1];
__device__ float   g_k2;

// ---------------- helpers ----------------
__device__ __forceinline__ unsigned h2u(__half2 h) { return *(unsigned*)&h; }
__device__ __forceinline__ float leaky(float x) { return x > 0.f ? x : 0.2f * x; }
__device__ __forceinline__ float elu(float x)   { return x > 0.f ? x : expm1f(x); }
__device__ __forceinline__ float wexp(float x)  { return __expf(fminf(x, 80.f)); }

// ---------------- fp16 W1 conversion ----------------
__global__ void convW1_kernel(const float* __restrict__ W1) {
    int i = blockIdx.x * blockDim.x + threadIdx.x;
    if (i >= INC * HC / 8) return;
    const float4* p = (const float4*)W1 + (size_t)i * 2;
    float4 a = p[0], b = p[1];
    uint4 u;
    u.x = h2u(__floats2half2_rn(a.x, a.y));
    u.y = h2u(__floats2half2_rn(a.z, a.w));
    u.z = h2u(__floats2half2_rn(b.x, b.y));
    u.w = h2u(__floats2half2_rn(b.z, b.w));
    ((uint4*)g_W1h)[i] = u;
}

// ---------------- GEMM1 + post1 fused: wmma -> smem -> dots + quad mirror ----------
#define CLD 136   // smem ld for C tile (halves)
__global__ void __launch_bounds__(256) sgemm1_fused(const float* __restrict__ x,
                                                    const float* __restrict__ as1,
                                                    const float* __restrict__ ad1) {
    __shared__ __align__(32) __half As[128][32];     // 8KB
    __shared__ __align__(32) __half Bs[16][144];     // 4.5KB
    __shared__ __align__(32) __half Cs[128][CLD];    // 34KB
    int tid = threadIdx.x;
    int w = tid >> 5, wr = w >> 1, wc = w & 1;
    int brow = blockIdx.x;

    wmma::fragment<wmma::accumulator, 16, 16, 16, float> cf[2][4];
#pragma unroll
    for (int mi = 0; mi < 2; mi++)
#pragma unroll
        for (int ni = 0; ni < 4; ni++) wmma::fill_fragment(cf[mi][ni], 0.f);

    int rA = tid >> 1, segA = (tid & 1) * 8;
    int ag = brow * 128 + rA;
    int qB = tid >> 4, cB = (tid & 15) * 8;

    for (int k0 = 0; k0 < INC; k0 += 16) {
        uint4 ua = make_uint4(0, 0, 0, 0);
        if (ag < NN) {
            const float* xp = x + (size_t)ag * INC + k0 + segA;
            float4 f0 = *(const float4*)(xp);
            float4 f1 = *(const float4*)(xp + 4);
            ua.x = h2u(__floats2half2_rn(f0.x, f0.y));
            ua.y = h2u(__floats2half2_rn(f0.z, f0.w));
            ua.z = h2u(__floats2half2_rn(f1.x, f1.y));
            ua.w = h2u(__floats2half2_rn(f1.z, f1.w));
        }
        *(uint4*)&As[rA][segA] = ua;
        *(uint4*)&Bs[qB][cB] = *(const uint4*)(g_W1h + (size_t)(k0 + qB) * HC + cB);
        __syncthreads();

        wmma::fragment<wmma::matrix_b, 16, 16, 16, __half, wmma::row_major> bf[4];
#pragma unroll
        for (int ni = 0; ni < 4; ni++)
            wmma::load_matrix_sync(bf[ni], &Bs[0][wc * 64 + ni * 16], 144);
#pragma unroll
        for (int mi = 0; mi < 2; mi++) {
            wmma::fragment<wmma::matrix_a, 16, 16, 16, __half, wmma::row_major> af;
            wmma::load_matrix_sync(af, &As[wr * 32 + mi * 16][0], 32);
#pragma unroll
            for (int ni = 0; ni < 4; ni++)
                wmma::mma_sync(cf[mi][ni], af, bf[ni], cf[mi][ni]);
        }
        __syncthreads();
    }

    // store accumulators as fp16 into smem C tile
#pragma unroll
    for (int mi = 0; mi < 2; mi++)
#pragma unroll
        for (int ni = 0; ni < 4; ni++) {
            wmma::fragment<wmma::accumulator, 16, 16, 16, __half> hf;
#pragma unroll
            for (int el = 0; el < hf.num_elements; el++)
                hf.x[el] = __float2half_rn(cf[mi][ni].x[el]);
            wmma::store_matrix_sync(&Cs[wr * 32 + mi * 16][wc * 64 + ni * 16],
                                    hf, CLD, wmma::mem_row_major);
        }
    __syncthreads();

    // fused post1: thread (r, q) handles row r = tid>>1, channel group q = tid&1
    int r = tid >> 1, q = tid & 1;
    int n = brow * 128 + r;
    if (n >= NN) return;
    const __half* crow = &Cs[r][0];

    float s[4], d[4];
    float v[4][16];
#pragma unroll
    for (int h = 0; h < 4; h++) {
        s[h] = 0.f; d[h] = 0.f;
#pragma unroll
        for (int g = 0; g < 8; g++) {
            int off = h * 32 + q * 16 + g * 2;
            float2 xv = __half22float2(*(const __half2*)(crow + off));
            v[h][g * 2] = xv.x; v[h][g * 2 + 1] = xv.y;
            float2 av = *(const float2*)(as1 + off);
            float2 dv = *(const float2*)(ad1 + off);
            s[h] += xv.x * av.x + xv.y * av.y;
            d[h] += xv.x * dv.x + xv.y * dv.y;
        }
    }
    // quad mirror: [n][c] = (x[c], x[c+32] | x[c+64], x[c+96]), c = q*16 + j
    uint2* op = g_xs1q + (size_t)n * 32 + q * 16;
#pragma unroll
    for (int j = 0; j < 16; j++) {
        op[j] = make_uint2(h2u(__floats2half2_rn(v[0][j], v[1][j])),
                           h2u(__floats2half2_rn(v[2][j], v[3][j])));
    }
    // combine partner partials (threads 2r / 2r+1 adjacent lanes)
#pragma unroll
    for (int h = 0; h < 4; h++) {
        s[h] += __shfl_xor_sync(0xffffffffu, s[h], 1);
        d[h] += __shfl_xor_sync(0xffffffffu, d[h], 1);
    }
    if (q == 0) {
#pragma unroll
        for (int h = 0; h < 4; h++) {
            g_als1[n * 4 + h] = s[h];
            g_ald1[n * 4 + h] = d[h];
        }
    }
}

// ---------------- CSR build (branch B) ----------------
__global__ void init_deg_kernel() {
    int i = blockIdx.x * blockDim.x + threadIdx.x;
    if (i < NN) g_deg[i] = 1;
}

__global__ void hist_mean_kernel(const int* __restrict__ ei, const float* __restrict__ ea) {
    __shared__ float s[256];
    float v = 0.f;
    for (int e = blockIdx.x * blockDim.x + threadIdx.x; e < EE; e += gridDim.x * blockDim.x) {
        atomicAdd(&g_deg[ei[EE + e]], 1);
        v += ea[e];
    }
    s[threadIdx.x] = v; __syncthreads();
    for (int o = 128; o > 0; o >>= 1) {
        if (threadIdx.x < o) s[threadIdx.x] += s[threadIdx.x + o];
        __syncthreads();
    }
    if (threadIdx.x == 0) g_partial[blockIdx.x] = s[0];
}

__global__ void mean_fin_kernel(const float* __restrict__ We1, const float* __restrict__ ae1,
                                const float* __restrict__ We2, const float* __restrict__ ae2) {
    __shared__ float s[512];
    int t = threadIdx.x;
    s[t] = g_partial[t]; __syncthreads();
    for (int o = 256; o > 0; o >>= 1) {
        if (t < o) s[t] += s[t + o];
        __syncthreads();
    }
    if (t == 0) g_mean = s[0] / (float)EE;
    if (t < H1) {
        float k = 0.f;
        for (int c = 0; c < C1; c++) k += We1[t * C1 + c] * ae1[t * C1 + c];
        g_k1v[t] = k;
    }
    if (t == H1) {
        float k = 0.f;
        for (int c = 0; c < C1; c++) k += We2[c] * ae2[c];
        g_k2 = k;
    }
}

__global__ void scan_part_kernel() {
    __shared__ int s[256];
    int t = threadIdx.x, b = blockIdx.x;
    int i = b * 256 + t;
    int v = (i < NN) ? g_deg[i] : 0;
    s[t] = v; __syncthreads();
    for (int o = 128; o > 0; o >>= 1) {
        if (t < o) s[t] += s[t + o];
        __syncthreads();
    }
    if (t == 0) g_bsum[b] = s[0];
}

__global__ void scan_mid_kernel() {
    __shared__ int s[256];
    int t = threadIdx.x;
    int v = (t < NB) ? g_bsum[t] : 0;
    s[t] = v; __syncthreads();
    for (int o = 1; o < 256; o <<= 1) {
        int u = (t >= o) ? s[t - o] : 0;
        __syncthreads();
        s[t] += u;
        __syncthreads();
    }
    if (t < NB) g_boff[t] = s[t] - v;
}

__global__ void scan_fin_kernel() {
    __shared__ int s[256];
    int t = threadIdx.x, b = blockIdx.x;
    int i = b * 256 + t;
    int v = (i < NN) ? g_deg[i] : 0;
    s[t] = v; __syncthreads();
    for (int o = 1; o < 256; o <<= 1) {
        int u = (t >= o) ? s[t - o] : 0;
        __syncthreads();
        s[t] += u;
        __syncthreads();
    }
    int excl = s[t] - v + g_boff[b];
    if (i < NN) { g_rowptr[i] = excl; g_cursor[i] = excl; }
    if (b == 0 && t == 0) g_rowptr[NN] = ET;
}

// ---------------- scatter: (src, ea) into 8B slots ----------------
__global__ void scatter_perm_kernel(const int* __restrict__ ei, const float* __restrict__ ea) {
    float mn = g_mean;
    for (int idx = blockIdx.x * blockDim.x + threadIdx.x; idx < ET; idx += gridDim.x * blockDim.x) {
        int srcn, dstn; float eav;
        if (idx < EE) {
            srcn = ei[idx];
            dstn = ei[EE + idx];
            eav  = ea[idx];
        } else {
            srcn = dstn = idx - EE;
            eav  = mn;
        }
        int slot = atomicAdd(&g_cursor[dstn], 1);
        g_slot[slot] = make_int2(srcn, __float_as_int(eav));
    }
}

// ---------------- agg1 + gemm2 + al2, fully fused (warp per node) ----------------
__global__ void __launch_bounds__(256) agg1_gemm2_kernel(
        const float* __restrict__ b1, const float* __restrict__ g1,
        const float* __restrict__ be1, const float* __restrict__ W2,
        const float* __restrict__ as2, const float* __restrict__ ad2) {
    __shared__ float  Ws[HC * C1];     // 16KB
    __shared__ float4 sw[8][32];       // 4KB
    __shared__ int    ssrc[8][32];     // 1KB
    __shared__ float  sh1[8][HC];      // 4KB
    int tid = threadIdx.x;
    for (int i = tid; i < HC * C1; i += blockDim.x) Ws[i] = W2[i];
    __syncthreads();

    int wi   = tid >> 5;
    int lane = tid & 31;
    int n    = blockIdx.x * 8 + wi;
    if (n >= NN) return;
    int beg = g_rowptr[n], end = g_rowptr[n + 1];
    float4 ald = *(const float4*)(g_ald1 + n * 4);
    float k0 = g_k1v[0], k1 = g_k1v[1], k2 = g_k1v[2], k3 = g_k1v[3];

    float acc0 = 0.f, acc1 = 0.f, acc2 = 0.f, acc3 = 0.f;
    float den0 = 0.f, den1 = 0.f, den2 = 0.f, den3 = 0.f;

    for (int c0 = beg; c0 < end; c0 += 32) {
        int m = end - c0; if (m > 32) m = 32;
        if (lane < m) {
            int2 se = g_slot[c0 + lane];
            float4 als = *(const float4*)(g_als1 + se.x * 4);
            float eav = __int_as_float(se.y);
            float4 w;
            w.x = wexp(leaky(als.x + ald.x + k0 * eav));
            w.y = wexp(leaky(als.y + ald.y + k1 * eav));
            w.z = wexp(leaky(als.z + ald.z + k2 * eav));
            w.w = wexp(leaky(als.w + ald.w + k3 * eav));
            sw[wi][lane] = w;
            ssrc[wi][lane] = se.x;
        }
        __syncwarp();
        for (int i = 0; i < m; i++) {
            float4 w = sw[wi][i];
            int s = ssrc[wi][i];
            uint2 xv = g_xs1q[(size_t)s * 32 + lane];
            float2 x01 = __half22float2(*(__half2*)&xv.x);   // (head0, head1)
            float2 x23 = __half22float2(*(__half2*)&xv.y);   // (head2, head3)
            acc0 += w.x * x01.x;  den0 += w.x;
            acc1 += w.y * x01.y;  den1 += w.y;
            acc2 += w.z * x23.x;  den2 += w.z;
            acc3 += w.w * x23.y;  den3 += w.w;
        }
        __syncwarp();
    }

    float inv = rsqrtf(1.f + BN_EPS);
#pragma unroll
    for (int h = 0; h < 4; h++) {
        float a = (h == 0) ? acc0 : (h == 1) ? acc1 : (h == 2) ? acc2 : acc3;
        float d = (h == 0) ? den0 : (h == 1) ? den1 : (h == 2) ? den2 : den3;
        int c = h * 32 + lane;
        float v = a / (d + 1e-16f) + b1[c];
        v = v * (g1[c] * inv) + be1[c];
        sh1[wi][c] = elu(v);
    }
    __syncwarp();

    float s2 = 0.f;
    const float* hp = sh1[wi];
#pragma unroll 8
    for (int k = 0; k < HC; k++) s2 += hp[k] * Ws[k * C1 + lane];
    g_xs2h[(size_t)n * C1 + lane] = __float2half_rn(s2);

    float ps = s2 * as2[lane];
    float pd = s2 * ad2[lane];
#pragma unroll
    for (int off = 16; off > 0; off >>= 1) {
        ps += __shfl_xor_sync(0xffffffffu, ps, off);
        pd += __shfl_xor_sync(0xffffffffu, pd, off);
    }
    if (lane == 0) { g_als2[n] = ps; g_ald2[n] = pd; }
}

// ---------------- agg2: warp/node, smem-staged weights + bn+elu + heads ----------
__global__ void agg2_heads_kernel(const float* __restrict__ b2, const float* __restrict__ g2,
                                  const float* __restrict__ be2,
                                  const float* __restrict__ Wc1, const float* __restrict__ bc1,
                                  const float* __restrict__ Wc2, const float* __restrict__ bc2,
                                  const float* __restrict__ Wr1, const float* __restrict__ br1,
                                  const float* __restrict__ Wr2, const float* __restrict__ br2,
                                  float* __restrict__ out) {
    __shared__ float sWc1[C1 * 16], sWr1[C1 * 16];
    __shared__ float sWc2[32], sWr2[16];
    __shared__ float sbc1[16], sbr1[16], sbc2[2], sbr2v[1];
    __shared__ float sh[8][32];
    __shared__ float sw2[8][32];
    __shared__ int   ssrc2[8][32];
    int t = threadIdx.x;
    for (int i = t; i < C1 * 16; i += blockDim.x) { sWc1[i] = Wc1[i]; sWr1[i] = Wr1[i]; }
    if (t < 32) sWc2[t] = Wc2[t];
    if (t < 16) { sWr2[t] = Wr2[t]; sbc1[t] = bc1[t]; sbr1[t] = br1[t]; }
    if (t < 2)  sbc2[t] = bc2[t];
    if (t == 32) sbr2v[0] = br2[0];
    __syncthreads();

    int wi   = t >> 5;
    int lane = t & 31;
    int n    = blockIdx.x * 8 + wi;
    if (n >= NN) return;
    int beg = g_rowptr[n], end = g_rowptr[n + 1];
    float ald = g_ald2[n];
    float k2  = g_k2;

    float den = 0.f, acc = 0.f;
    for (int c0 = beg; c0 < end; c0 += 32) {
        int m = end - c0; if (m > 32) m = 32;
        if (lane < m) {
            int2 se = g_slot[c0 + lane];
            sw2[wi][lane] = wexp(leaky(g_als2[se.x] + ald + k2 * __int_as_float(se.y)));
            ssrc2[wi][lane] = se.x;
        }
        __syncwarp();
        for (int i = 0; i < m; i++) {
            float w = sw2[wi][i];
            int s = ssrc2[wi][i];
            acc += w * __half2float(g_xs2h[(size_t)s * C1 + lane]);
            den += w;
        }
        __syncwarp();
    }
    float v = acc / (den + 1e-16f) + b2[lane];
    v = v * (g2[lane] * rsqrtf(1.f + BN_EPS)) + be2[lane];
    float h = elu(v);
    out[3 * NN + (size_t)n * C1 + lane] = h;
    sh[wi][lane] = h;
    __syncwarp();

    int j = lane & 15;
    const float* W = (lane < 16) ? sWc1 : sWr1;
    float tt = (lane < 16) ? sbc1[j] : sbr1[j];
#pragma unroll
    for (int c = 0; c < C1; c++) tt += sh[wi][c] * W[c * 16 + j];
    tt = fmaxf(tt, 0.f);
    float pa = (lane < 16) ? tt * sWc2[j * 2 + 0] : tt * sWr2[j];
    float pb = (lane < 16) ? tt * sWc2[j * 2 + 1] : 0.f;
#pragma unroll
    for (int off = 8; off > 0; off >>= 1) {
        pa += __shfl_xor_sync(0xffffffffu, pa, off);
        pb += __shfl_xor_sync(0xffffffffu, pb, off);
    }
    if (lane == 0) {
        out[(size_t)n * 2 + 0] = pa + sbc2[0];
        out[(size_t)n * 2 + 1] = pb + sbc2[1];
    }
    if (lane == 16) {
        out[2 * NN + n] = pa + sbr2v[0];
    }
}

// ---------------- launch (stream-forked graph) ----------------
extern "C" void kernel_launch(void* const* d_in, const int* in_sizes, int n_in,
                              void* d_out, int out_size) {
    const float* x   = (const float*)d_in[0];
    const int*   ei  = (const int*)d_in[1];     // int32 (JAX x64 disabled)
    const float* ea  = (const float*)d_in[2];
    const float* W1  = (const float*)d_in[3];
    const float* as1 = (const float*)d_in[4];
    const float* ad1 = (const float*)d_in[5];
    const float* We1 = (const float*)d_in[6];
    const float* ae1 = (const float*)d_in[7];
    const float* b1  = (const float*)d_in[8];
    const float* g1  = (const float*)d_in[9];
    const float* be1 = (const float*)d_in[10];
    const float* W2  = (const float*)d_in[11];
    const float* as2 = (const float*)d_in[12];
    const float* ad2 = (const float*)d_in[13];
    const float* We2 = (const float*)d_in[14];
    const float* ae2 = (const float*)d_in[15];
    const float* b2  = (const float*)d_in[16];
    const float* g2  = (const float*)d_in[17];
    const float* be2 = (const float*)d_in[18];
    const float* Wc1 = (const float*)d_in[19];
    const float* bc1 = (const float*)d_in[20];
    const float* Wc2 = (const float*)d_in[21];
    const float* bc2 = (const float*)d_in[22];
    const float* Wr1 = (const float*)d_in[23];
    const float* br1 = (const float*)d_in[24];
    const float* Wr2 = (const float*)d_in[25];
    const float* br2 = (const float*)d_in[26];
    float* out = (float*)d_out;

    cudaStream_t sB;
    cudaStreamCreateWithFlags(&sB, cudaStreamNonBlocking);
    cudaEvent_t eFork, eJoin;
    cudaEventCreateWithFlags(&eFork, cudaEventDisableTiming);
    cudaEventCreateWithFlags(&eJoin, cudaEventDisableTiming);

    cudaEventRecord(eFork, 0);
    cudaStreamWaitEvent(sB, eFork, 0);

    // Branch B (CSR + scatter permutation)
    init_deg_kernel<<<(NN + 255) / 256, 256, 0, sB>>>();
    hist_mean_kernel<<<512, 256, 0, sB>>>(ei, ea);
    mean_fin_kernel<<<1, 512, 0, sB>>>(We1, ae1, We2, ae2);
    scan_part_kernel<<<NB, 256, 0, sB>>>();
    scan_mid_kernel<<<1, 256, 0, sB>>>();
    scan_fin_kernel<<<NB, 256, 0, sB>>>();
    scatter_perm_kernel<<<2048, 256, 0, sB>>>(ei, ea);

    // Branch A (fp16 GEMM1 + fused post1) on main stream
    convW1_kernel<<<(INC * HC / 8 + 255) / 256, 256>>>(W1);
    sgemm1_fused<<<(NN + 127) / 128, 256>>>(x, as1, ad1);

    cudaEventRecord(eJoin, sB);
    cudaStreamWaitEvent(0, eJoin, 0);

    // Joined tail on main stream
    agg1_gemm2_kernel<<<(NN + 7) / 8, 256>>>(b1, g1, be1, W2, as2, ad2);
    agg2_heads_kernel<<<(NN + 7) / 8, 256>>>(b2, g2, be2,
        Wc1, bc1, Wc2, bc2, Wr1, br1, Wr2, br2, out);

    cudaEventDestroy(eFork);
    cudaEventDestroy(eJoin);
    // sB intentionally not destroyed during capture.
}